// round 12
// baseline (speedup 1.0000x reference)
#include <cuda_runtime.h>
#include <cuda_bf16.h>
#include <cstddef>
#include <cstdint>

using bf16 = __nv_bfloat16;

// Problem constants
static constexpr int Bb    = 4;
static constexpr int Nn    = 4096;
static constexpr int Dd    = 1024;
static constexpr int Mrows = Bb * Nn;      // 16384
static constexpr int QKVN  = 3 * Dd;       // 3072
static constexpr int Kdim  = 1024;         // K of both GEMMs

// ---------------------------------------------------------------------------
// Scratch (__device__ globals; allocation-free rule)
// ---------------------------------------------------------------------------
__device__ float g_qkv[(size_t)Mrows * QKVN];          // fp32 qkv
__device__ bf16  g_xh [(size_t)Mrows * Dd], g_xl [(size_t)Mrows * Dd];
__device__ bf16  g_ah [(size_t)Mrows * Dd], g_al [(size_t)Mrows * Dd];
__device__ bf16  g_wqh[(size_t)QKVN  * Dd], g_wql[(size_t)QKVN  * Dd];
__device__ bf16  g_wfh[(size_t)Dd    * Dd], g_wfl[(size_t)Dd    * Dd];

// ---------------------------------------------------------------------------
// Helpers
// ---------------------------------------------------------------------------
__device__ __forceinline__ uint32_t smem_u32(const void* p) {
    return (uint32_t)__cvta_generic_to_shared(p);
}
__device__ __forceinline__ void ldsm4(uint32_t& r0, uint32_t& r1,
                                      uint32_t& r2, uint32_t& r3, uint32_t addr) {
    asm volatile("ldmatrix.sync.aligned.m8n8.x4.shared.b16 {%0,%1,%2,%3}, [%4];\n"
                 : "=r"(r0), "=r"(r1), "=r"(r2), "=r"(r3) : "r"(addr));
}
__device__ __forceinline__ void mma_bf16(float* c, const uint32_t* a, const uint32_t* b) {
    asm volatile(
        "mma.sync.aligned.m16n8k16.row.col.f32.bf16.bf16.f32 "
        "{%0,%1,%2,%3}, {%4,%5,%6,%7}, {%8,%9}, {%0,%1,%2,%3};\n"
        : "+f"(c[0]), "+f"(c[1]), "+f"(c[2]), "+f"(c[3])
        : "r"(a[0]), "r"(a[1]), "r"(a[2]), "r"(a[3]), "r"(b[0]), "r"(b[1]));
}
__device__ __forceinline__ void cp16(uint32_t dst, const void* src) {
    asm volatile("cp.async.cg.shared.global [%0], [%1], 16;" :: "r"(dst), "l"(src));
}
__device__ __forceinline__ void cp_commit() {
    asm volatile("cp.async.commit_group;" ::: "memory");
}
template <int N>
__device__ __forceinline__ void cp_wait() {
    asm volatile("cp.async.wait_group %0;" :: "n"(N) : "memory");
}
__device__ __forceinline__ void split_bf16(float v, bf16& h, bf16& l) {
    h = __float2bfloat16_rn(v);
    l = __float2bfloat16_rn(v - __bfloat162float(h));
}
__device__ __forceinline__ uint2 pack4(bf16 a, bf16 b, bf16 c, bf16 d) {
    uint2 r;
    uint16_t ua = *(uint16_t*)&a, ub = *(uint16_t*)&b;
    uint16_t uc = *(uint16_t*)&c, ud = *(uint16_t*)&d;
    r.x = (uint32_t)ua | ((uint32_t)ub << 16);
    r.y = (uint32_t)uc | ((uint32_t)ud << 16);
    return r;
}

// ---------------------------------------------------------------------------
// bf16x3 tensor-core GEMM (NT), cp.async 3-stage pipeline (R6 structure),
// templated on BM (64 or 128) to tune wave quantization. BN fixed at 128.
//   C[m][n] = sum_k A[m][k]*W[n][k] (+bias),  C ~= Ah*Wh + Al*Wh + Ah*Wl
// 8 warps: (BM/32) m-warps x (8/(BM/32)) n-warps, warp tile 32m x (128*BM/32/8?)
//   BM=128: 4m x 2n warps, warp tile 32x64 (NG=8)   -- identical to R6
//   BM=64 : 2m x 4n warps, warp tile 32x32 (NG=4)
// smem per stage: [Ah | Al | Wh | Wl]; rows x 64 B; XOR swizzle
// chunk' = chunk ^ ((row>>1)&3) on 16 B chunks.
// ---------------------------------------------------------------------------
static constexpr int BK      = 32;
static constexpr int KTILES  = Kdim / BK;        // 32
static constexpr int NSTAGE  = 3;

template <int BM_>
struct GemmCfg {
    static constexpr int TSZA  = BM_ * 64;           // A tile bytes
    static constexpr int TSZW  = 128 * 64;           // W tile bytes
    static constexpr int STAGE = 2 * TSZA + 2 * TSZW;
    static constexpr int SMEM  = NSTAGE * STAGE;
    static constexpr int MWARP = BM_ / 32;           // m-warps
    static constexpr int NWARP = 8 / MWARP;          // n-warps
    static constexpr int NW    = 128 / NWARP;        // warp n-width
    static constexpr int NG    = NW / 8;             // n-groups per warp
    static constexpr int NPAIR = NG / 2;             // ldsm4 B frag-pairs
    static constexpr int CHUNKS = STAGE / 16;        // 16B chunks per stage
    static constexpr int ITER  = CHUNKS / 256;       // per-thread cp16 count
};

template <int BM_, bool BIAS>
__global__ __launch_bounds__(256, 2)
void gemm_cp(const bf16* __restrict__ Ah, const bf16* __restrict__ Al,
             const bf16* __restrict__ Wh, const bf16* __restrict__ Wl,
             const float* __restrict__ bias, float* __restrict__ C, int Ndim)
{
    using Cfg = GemmCfg<BM_>;
    extern __shared__ char smem[];
    const uint32_t smem_base = smem_u32(smem);
    const int tid  = threadIdx.x;
    const int wid  = tid >> 5;
    const int lane = tid & 31;
    const int wr   = wid % Cfg::MWARP;      // m offset wr*32
    const int wc   = wid / Cfg::MWARP;      // n offset wc*NW
    const int m0   = blockIdx.y * BM_;
    const int n0   = blockIdx.x * 128;

    const bf16* src[4] = { Ah + (size_t)m0 * Kdim, Al + (size_t)m0 * Kdim,
                           Wh + (size_t)n0 * Kdim, Wl + (size_t)n0 * Kdim };

    // ---- cp.async mapping (Cfg::ITER chunks of 16 B per thread per stage) ----
    auto load_stage = [&](int t, int buf) {
        const int k0 = t * BK;
        const uint32_t sb = smem_base + buf * Cfg::STAGE;
        #pragma unroll
        for (int i = 0; i < Cfg::ITER; ++i) {
            const int idx = tid + i * 256;
            constexpr int ACH = BM_ * 4;           // chunks per A array
            int arr, row, ch;
            uint32_t base;
            if (idx < 2 * ACH) {
                arr  = (idx < ACH) ? 0 : 1;
                const int id2 = idx % ACH;
                row  = id2 >> 2;
                ch   = id2 & 3;
                base = arr * Cfg::TSZA;
            } else {
                const int w = idx - 2 * ACH;
                arr  = (w < 512) ? 2 : 3;
                const int id2 = w & 511;
                row  = id2 >> 2;
                ch   = id2 & 3;
                base = 2 * Cfg::TSZA + ((w < 512) ? 0 : Cfg::TSZW);
            }
            const uint32_t dst = sb + base + row * 64 +
                                 ((ch ^ ((row >> 1) & 3)) << 4);
            cp16(dst, src[arr] + (size_t)row * Kdim + k0 + ch * 8);
        }
        cp_commit();
    };

    // ---- ldmatrix offsets (within stage), per mi/gi and k-step ----
    const int tq   = lane >> 3;
    const int arow = (lane & 7) + (tq & 1) * 8;
    const int ach  = tq >> 1;
    const int brow = (tq >> 1) * 8 + (lane & 7);
    const int bch  = tq & 1;

    uint32_t offA[2][2], offB[Cfg::NPAIR][2];
    #pragma unroll
    for (int mi = 0; mi < 2; ++mi) {
        const int row = wr * 32 + mi * 16 + arow;
        #pragma unroll
        for (int ks = 0; ks < 2; ++ks) {
            const int ch = ach + ks * 2;
            offA[mi][ks] = row * 64 + (((ch ^ ((row >> 1) & 3))) << 4);
        }
    }
    #pragma unroll
    for (int gi = 0; gi < Cfg::NPAIR; ++gi) {
        const int row = wc * Cfg::NW + gi * 16 + brow;
        #pragma unroll
        for (int ks = 0; ks < 2; ++ks) {
            const int ch = bch + ks * 2;
            offB[gi][ks] = row * 64 + (((ch ^ ((row >> 1) & 3))) << 4);
        }
    }

    float acc[2][Cfg::NG][4];
    #pragma unroll
    for (int i = 0; i < 2; ++i)
        #pragma unroll
        for (int j = 0; j < Cfg::NG; ++j)
            #pragma unroll
            for (int e = 0; e < 4; ++e) acc[i][j][e] = 0.f;

    // ---- prologue: fill the pipeline ----
    load_stage(0, 0);
    load_stage(1, 1);
    load_stage(2, 2);

    for (int t = 0; t < KTILES; ++t) {
        cp_wait<2>();              // stage t landed
        __syncthreads();

        const int buf = t % NSTAGE;
        const uint32_t sa = smem_base + buf * Cfg::STAGE;        // Ah base
        const uint32_t sw = sa + 2 * Cfg::TSZA;                  // Wh base

        #pragma unroll
        for (int ks = 0; ks < 2; ++ks) {
            uint32_t af[2][4], alf[2][4], bfr[Cfg::NPAIR][4];
            // pass 1: Ah x Wh
            #pragma unroll
            for (int mi = 0; mi < 2; ++mi)
                ldsm4(af[mi][0], af[mi][1], af[mi][2], af[mi][3], sa + offA[mi][ks]);
            #pragma unroll
            for (int gi = 0; gi < Cfg::NPAIR; ++gi)
                ldsm4(bfr[gi][0], bfr[gi][1], bfr[gi][2], bfr[gi][3], sw + offB[gi][ks]);
            #pragma unroll
            for (int mi = 0; mi < 2; ++mi)
                #pragma unroll
                for (int g = 0; g < Cfg::NG; ++g)
                    mma_bf16(acc[mi][g], af[mi], &bfr[g >> 1][(g & 1) * 2]);
            // pass 2: Al x Wh
            #pragma unroll
            for (int mi = 0; mi < 2; ++mi)
                ldsm4(alf[mi][0], alf[mi][1], alf[mi][2], alf[mi][3],
                      sa + Cfg::TSZA + offA[mi][ks]);
            #pragma unroll
            for (int mi = 0; mi < 2; ++mi)
                #pragma unroll
                for (int g = 0; g < Cfg::NG; ++g)
                    mma_bf16(acc[mi][g], alf[mi], &bfr[g >> 1][(g & 1) * 2]);
            // pass 3: Ah x Wl
            #pragma unroll
            for (int gi = 0; gi < Cfg::NPAIR; ++gi)
                ldsm4(bfr[gi][0], bfr[gi][1], bfr[gi][2], bfr[gi][3],
                      sw + Cfg::TSZW + offB[gi][ks]);
            #pragma unroll
            for (int mi = 0; mi < 2; ++mi)
                #pragma unroll
                for (int g = 0; g < Cfg::NG; ++g)
                    mma_bf16(acc[mi][g], af[mi], &bfr[g >> 1][(g & 1) * 2]);
        }

        __syncthreads();
        if (t + NSTAGE < KTILES) load_stage(t + NSTAGE, buf);
    }

    // ---- epilogue (m16n8 C-frag layout) ----
    const int crow = lane >> 2;
    const int ccol = (lane & 3) * 2;
    #pragma unroll
    for (int mi = 0; mi < 2; ++mi) {
        #pragma unroll
        for (int g = 0; g < Cfg::NG; ++g) {
            const int col = n0 + wc * Cfg::NW + g * 8 + ccol;
            float b0 = BIAS ? bias[col]     : 0.f;
            float b1 = BIAS ? bias[col + 1] : 0.f;
            const int r0 = m0 + wr * 32 + mi * 16 + crow;
            float2 v0 = make_float2(acc[mi][g][0] + b0, acc[mi][g][1] + b1);
            float2 v1 = make_float2(acc[mi][g][2] + b0, acc[mi][g][3] + b1);
            *(float2*)(C + (size_t)r0 * Ndim + col)       = v0;
            *(float2*)(C + (size_t)(r0 + 8) * Ndim + col) = v1;
        }
    }
}

// ---------------------------------------------------------------------------
// Fused fp32 -> hi/lo bf16 split for all three tensors (one launch)
// ---------------------------------------------------------------------------
static constexpr int N4X = Mrows * Dd / 4;   // x
static constexpr int N4Q = QKVN  * Dd / 4;   // w_qkv
static constexpr int N4F = Dd    * Dd / 4;   // w_fc
static constexpr int N4ALL = N4X + N4Q + N4F;

__device__ __forceinline__ void split4(const float* __restrict__ s,
                                       bf16* __restrict__ h, bf16* __restrict__ l,
                                       int i) {
    float4 v = *(const float4*)(s + (size_t)i * 4);
    bf16 h0,h1,h2,h3,l0,l1,l2,l3;
    split_bf16(v.x,h0,l0); split_bf16(v.y,h1,l1);
    split_bf16(v.z,h2,l2); split_bf16(v.w,h3,l3);
    *(uint2*)(h + (size_t)i * 4) = pack4(h0,h1,h2,h3);
    *(uint2*)(l + (size_t)i * 4) = pack4(l0,l1,l2,l3);
}

__global__ void convert_all(const float* __restrict__ x,
                            const float* __restrict__ wq,
                            const float* __restrict__ wf,
                            bf16* __restrict__ xh, bf16* __restrict__ xl,
                            bf16* __restrict__ wqh, bf16* __restrict__ wql,
                            bf16* __restrict__ wfh, bf16* __restrict__ wfl)
{
    const int i = blockIdx.x * blockDim.x + threadIdx.x;
    if (i < N4X)               split4(x,  xh,  xl,  i);
    else if (i < N4X + N4Q)    split4(wq, wqh, wql, i - N4X);
    else if (i < N4ALL)        split4(wf, wfh, wfl, i - N4X - N4Q);
}

// ---------------------------------------------------------------------------
// Attention (faithful-reshape 16x16 head-mixing), one CTA per (b, r, j):
//   q_prep[b, n, h, dh] = q[b, h*256 + n/16, (n%16)*64 + dh]
// fp32 qkv in, hi/lo bf16 out.
// ---------------------------------------------------------------------------
__global__ __launch_bounds__(256)
void attn16_kernel(const float* __restrict__ qkv,
                   bf16* __restrict__ oh, bf16* __restrict__ ol)
{
    const int bxi = blockIdx.x;          // b*4096 + r*16 + j
    const int j = bxi & 15;
    const int r = (bxi >> 4) & 255;
    const int b = bxi >> 12;
    const int tid = threadIdx.x;
    const int hh = tid >> 4;
    const int lo = tid & 15;

    __shared__ float qs[16][64];
    __shared__ float ks[16][65];
    __shared__ float vs[16][64];
    __shared__ float ps[16][17];

    const size_t rowbase = ((size_t)b * 4096 + (size_t)hh * 256 + r) * 3072;
    const size_t outbase = ((size_t)b * 4096 + (size_t)hh * 256 + r) * 1024;
    const float scale = 0.125f;

    {
        const size_t c = (size_t)j * 64 + lo * 4;
        float4 q4 = *(const float4*)(qkv + rowbase + 0    + c);
        float4 k4 = *(const float4*)(qkv + rowbase + 1024 + c);
        float4 v4 = *(const float4*)(qkv + rowbase + 2048 + c);
        *(float4*)&qs[hh][lo * 4] = q4;
        ks[hh][lo * 4 + 0] = k4.x; ks[hh][lo * 4 + 1] = k4.y;
        ks[hh][lo * 4 + 2] = k4.z; ks[hh][lo * 4 + 3] = k4.w;
        *(float4*)&vs[hh][lo * 4] = v4;
    }
    __syncthreads();

    float s = 0.f;
    #pragma unroll
    for (int d = 0; d < 64; ++d) s = fmaf(qs[hh][d], ks[lo][d], s);
    s *= scale;

    float mx = s;
    #pragma unroll
    for (int off = 8; off; off >>= 1)
        mx = fmaxf(mx, __shfl_xor_sync(0xffffffffu, mx, off, 16));
    float e = __expf(s - mx);
    float sum = e;
    #pragma unroll
    for (int off = 8; off; off >>= 1)
        sum += __shfl_xor_sync(0xffffffffu, sum, off, 16);
    ps[hh][lo] = e / sum;
    __syncthreads();

    float4 o = make_float4(0.f, 0.f, 0.f, 0.f);
    #pragma unroll
    for (int g = 0; g < 16; ++g) {
        const float p = ps[hh][g];
        float4 v4 = *(const float4*)&vs[g][lo * 4];
        o.x = fmaf(p, v4.x, o.x); o.y = fmaf(p, v4.y, o.y);
        o.z = fmaf(p, v4.z, o.z); o.w = fmaf(p, v4.w, o.w);
    }
    bf16 h0,h1,h2,h3,l0,l1,l2,l3;
    split_bf16(o.x,h0,l0); split_bf16(o.y,h1,l1);
    split_bf16(o.z,h2,l2); split_bf16(o.w,h3,l3);
    *(uint2*)(oh + outbase + (size_t)j * 64 + lo * 4) = pack4(h0,h1,h2,h3);
    *(uint2*)(ol + outbase + (size_t)j * 64 + lo * 4) = pack4(l0,l1,l2,l3);
}

// ---------------------------------------------------------------------------
// Launch
// ---------------------------------------------------------------------------
extern "C" void kernel_launch(void* const* d_in, const int* in_sizes, int n_in,
                              void* d_out, int out_size)
{
    const float* x     = (const float*)d_in[0];  // (4, 4096, 1024)
    const float* w_qkv = (const float*)d_in[1];  // (3072, 1024)
    const float* w_fc  = (const float*)d_in[2];  // (1024, 1024)
    const float* b_fc  = (const float*)d_in[3];  // (1024,)
    float* out = (float*)d_out;                  // (4, 4096, 1024)

    float *qkv_p; bf16 *xh_p, *xl_p, *ah_p, *al_p, *wqh_p, *wql_p, *wfh_p, *wfl_p;
    cudaGetSymbolAddress((void**)&qkv_p, g_qkv);
    cudaGetSymbolAddress((void**)&xh_p,  g_xh);  cudaGetSymbolAddress((void**)&xl_p,  g_xl);
    cudaGetSymbolAddress((void**)&ah_p,  g_ah);  cudaGetSymbolAddress((void**)&al_p,  g_al);
    cudaGetSymbolAddress((void**)&wqh_p, g_wqh); cudaGetSymbolAddress((void**)&wql_p, g_wql);
    cudaGetSymbolAddress((void**)&wfh_p, g_wfh); cudaGetSymbolAddress((void**)&wfl_p, g_wfl);

    constexpr int SMEM64 = GemmCfg<64>::SMEM;   // 73728 B
    cudaFuncSetAttribute(gemm_cp<64,false>, cudaFuncAttributeMaxDynamicSharedMemorySize, SMEM64);
    cudaFuncSetAttribute(gemm_cp<64,true>,  cudaFuncAttributeMaxDynamicSharedMemorySize, SMEM64);

    // 0) split inputs/weights into hi/lo bf16 (single fused launch)
    convert_all<<<(N4ALL + 255) / 256, 256>>>(x, w_qkv, w_fc,
                                              xh_p, xl_p, wqh_p, wql_p, wfh_p, wfl_p);

    // 1) qkv = x @ w_qkv^T  (M=16384, N=3072): 24 x 256 = 6144 tiles (BM=64)
    gemm_cp<64,false><<<dim3(QKVN / 128, Mrows / 64), 256, SMEM64>>>(
        xh_p, xl_p, wqh_p, wql_p, nullptr, qkv_p, QKVN);

    // 2) 16x16 head-mix attention -> hi/lo bf16 (one CTA per (b,r,j))
    attn16_kernel<<<Bb * 256 * 16, 256>>>(qkv_p, ah_p, al_p);

    // 3) out = attn @ w_fc^T + b_fc  (M=16384, N=1024): 8 x 256 = 2048 tiles
    gemm_cp<64,true><<<dim3(Dd / 128, Mrows / 64), 256, SMEM64>>>(
        ah_p, al_p, wfh_p, wfl_p, b_fc, out, Dd);
}

// round 13
// speedup vs baseline: 1.0854x; 1.0854x over previous
#include <cuda_runtime.h>
#include <cuda_bf16.h>
#include <cstddef>
#include <cstdint>

using bf16 = __nv_bfloat16;

// Problem constants
static constexpr int Bb    = 4;
static constexpr int Nn    = 4096;
static constexpr int Dd    = 1024;
static constexpr int Mrows = Bb * Nn;      // 16384
static constexpr int QKVN  = 3 * Dd;       // 3072
static constexpr int Kdim  = 1024;         // K of both GEMMs

// ---------------------------------------------------------------------------
// Scratch (__device__ globals; allocation-free rule)
// ---------------------------------------------------------------------------
__device__ float g_qkv[(size_t)Mrows * QKVN];          // fp32 qkv
__device__ bf16  g_xh [(size_t)Mrows * Dd], g_xl [(size_t)Mrows * Dd];
__device__ bf16  g_ah [(size_t)Mrows * Dd], g_al [(size_t)Mrows * Dd];
__device__ bf16  g_wqh[(size_t)QKVN  * Dd], g_wql[(size_t)QKVN  * Dd];
__device__ bf16  g_wfh[(size_t)Dd    * Dd], g_wfl[(size_t)Dd    * Dd];

// ---------------------------------------------------------------------------
// Helpers
// ---------------------------------------------------------------------------
__device__ __forceinline__ uint32_t smem_u32(const void* p) {
    return (uint32_t)__cvta_generic_to_shared(p);
}
__device__ __forceinline__ void ldsm4(uint32_t& r0, uint32_t& r1,
                                      uint32_t& r2, uint32_t& r3, uint32_t addr) {
    asm volatile("ldmatrix.sync.aligned.m8n8.x4.shared.b16 {%0,%1,%2,%3}, [%4];\n"
                 : "=r"(r0), "=r"(r1), "=r"(r2), "=r"(r3) : "r"(addr));
}
__device__ __forceinline__ void mma_bf16(float* c, const uint32_t* a, const uint32_t* b) {
    asm volatile(
        "mma.sync.aligned.m16n8k16.row.col.f32.bf16.bf16.f32 "
        "{%0,%1,%2,%3}, {%4,%5,%6,%7}, {%8,%9}, {%0,%1,%2,%3};\n"
        : "+f"(c[0]), "+f"(c[1]), "+f"(c[2]), "+f"(c[3])
        : "r"(a[0]), "r"(a[1]), "r"(a[2]), "r"(a[3]), "r"(b[0]), "r"(b[1]));
}
__device__ __forceinline__ void cp16(uint32_t dst, const void* src) {
    asm volatile("cp.async.cg.shared.global [%0], [%1], 16;" :: "r"(dst), "l"(src));
}
__device__ __forceinline__ void cp_commit() {
    asm volatile("cp.async.commit_group;" ::: "memory");
}
template <int N>
__device__ __forceinline__ void cp_wait() {
    asm volatile("cp.async.wait_group %0;" :: "n"(N) : "memory");
}
__device__ __forceinline__ void split_bf16(float v, bf16& h, bf16& l) {
    h = __float2bfloat16_rn(v);
    l = __float2bfloat16_rn(v - __bfloat162float(h));
}
__device__ __forceinline__ uint2 pack4(bf16 a, bf16 b, bf16 c, bf16 d) {
    uint2 r;
    uint16_t ua = *(uint16_t*)&a, ub = *(uint16_t*)&b;
    uint16_t uc = *(uint16_t*)&c, ud = *(uint16_t*)&d;
    r.x = (uint32_t)ua | ((uint32_t)ub << 16);
    r.y = (uint32_t)uc | ((uint32_t)ud << 16);
    return r;
}

// ---------------------------------------------------------------------------
// bf16x3 tensor-core GEMM (NT), cp.async 3-stage pipeline (R6 structure),
// templated on BM. BM=128 instantiation is bit-identical to the best-known
// R6/R11 kernel (4m x 2n warps, warp tile 32x64, NG=8).
//   C[m][n] = sum_k A[m][k]*W[n][k] (+bias),  C ~= Ah*Wh + Al*Wh + Ah*Wl
// smem per stage: [Ah | Al | Wh | Wl]; rows x 64 B; XOR swizzle
// chunk' = chunk ^ ((row>>1)&3) on 16 B chunks.
// ---------------------------------------------------------------------------
static constexpr int BK      = 32;
static constexpr int KTILES  = Kdim / BK;        // 32
static constexpr int NSTAGE  = 3;

template <int BM_>
struct GemmCfg {
    static constexpr int TSZA  = BM_ * 64;           // A tile bytes
    static constexpr int TSZW  = 128 * 64;           // W tile bytes
    static constexpr int STAGE = 2 * TSZA + 2 * TSZW;
    static constexpr int SMEM  = NSTAGE * STAGE;
    static constexpr int MWARP = BM_ / 32;           // m-warps
    static constexpr int NWARP = 8 / MWARP;          // n-warps
    static constexpr int NW    = 128 / NWARP;        // warp n-width
    static constexpr int NG    = NW / 8;             // n-groups per warp
    static constexpr int NPAIR = NG / 2;             // ldsm4 B frag-pairs
    static constexpr int CHUNKS = STAGE / 16;        // 16B chunks per stage
    static constexpr int ITER  = CHUNKS / 256;       // per-thread cp16 count
};

template <int BM_, bool BIAS>
__global__ __launch_bounds__(256, 2)
void gemm_cp(const bf16* __restrict__ Ah, const bf16* __restrict__ Al,
             const bf16* __restrict__ Wh, const bf16* __restrict__ Wl,
             const float* __restrict__ bias, float* __restrict__ C, int Ndim)
{
    using Cfg = GemmCfg<BM_>;
    extern __shared__ char smem[];
    const uint32_t smem_base = smem_u32(smem);
    const int tid  = threadIdx.x;
    const int wid  = tid >> 5;
    const int lane = tid & 31;
    const int wr   = wid % Cfg::MWARP;      // m offset wr*32
    const int wc   = wid / Cfg::MWARP;      // n offset wc*NW
    const int m0   = blockIdx.y * BM_;
    const int n0   = blockIdx.x * 128;

    const bf16* src[4] = { Ah + (size_t)m0 * Kdim, Al + (size_t)m0 * Kdim,
                           Wh + (size_t)n0 * Kdim, Wl + (size_t)n0 * Kdim };

    // ---- cp.async mapping (Cfg::ITER chunks of 16 B per thread per stage) ----
    auto load_stage = [&](int t, int buf) {
        const int k0 = t * BK;
        const uint32_t sb = smem_base + buf * Cfg::STAGE;
        #pragma unroll
        for (int i = 0; i < Cfg::ITER; ++i) {
            const int idx = tid + i * 256;
            constexpr int ACH = BM_ * 4;           // chunks per A array
            int arr, row, ch;
            uint32_t base;
            if (idx < 2 * ACH) {
                arr  = (idx < ACH) ? 0 : 1;
                const int id2 = idx % ACH;
                row  = id2 >> 2;
                ch   = id2 & 3;
                base = arr * Cfg::TSZA;
            } else {
                const int w = idx - 2 * ACH;
                arr  = (w < 512) ? 2 : 3;
                const int id2 = w & 511;
                row  = id2 >> 2;
                ch   = id2 & 3;
                base = 2 * Cfg::TSZA + ((w < 512) ? 0 : Cfg::TSZW);
            }
            const uint32_t dst = sb + base + row * 64 +
                                 ((ch ^ ((row >> 1) & 3)) << 4);
            cp16(dst, src[arr] + (size_t)row * Kdim + k0 + ch * 8);
        }
        cp_commit();
    };

    // ---- ldmatrix offsets (within stage), per mi/gi and k-step ----
    const int tq   = lane >> 3;
    const int arow = (lane & 7) + (tq & 1) * 8;
    const int ach  = tq >> 1;
    const int brow = (tq >> 1) * 8 + (lane & 7);
    const int bch  = tq & 1;

    uint32_t offA[2][2], offB[Cfg::NPAIR][2];
    #pragma unroll
    for (int mi = 0; mi < 2; ++mi) {
        const int row = wr * 32 + mi * 16 + arow;
        #pragma unroll
        for (int ks = 0; ks < 2; ++ks) {
            const int ch = ach + ks * 2;
            offA[mi][ks] = row * 64 + (((ch ^ ((row >> 1) & 3))) << 4);
        }
    }
    #pragma unroll
    for (int gi = 0; gi < Cfg::NPAIR; ++gi) {
        const int row = wc * Cfg::NW + gi * 16 + brow;
        #pragma unroll
        for (int ks = 0; ks < 2; ++ks) {
            const int ch = bch + ks * 2;
            offB[gi][ks] = row * 64 + (((ch ^ ((row >> 1) & 3))) << 4);
        }
    }

    float acc[2][Cfg::NG][4];
    #pragma unroll
    for (int i = 0; i < 2; ++i)
        #pragma unroll
        for (int j = 0; j < Cfg::NG; ++j)
            #pragma unroll
            for (int e = 0; e < 4; ++e) acc[i][j][e] = 0.f;

    // ---- prologue: fill the pipeline ----
    load_stage(0, 0);
    load_stage(1, 1);
    load_stage(2, 2);

    for (int t = 0; t < KTILES; ++t) {
        cp_wait<2>();              // stage t landed
        __syncthreads();

        const int buf = t % NSTAGE;
        const uint32_t sa = smem_base + buf * Cfg::STAGE;        // Ah base
        const uint32_t sw = sa + 2 * Cfg::TSZA;                  // Wh base

        #pragma unroll
        for (int ks = 0; ks < 2; ++ks) {
            uint32_t af[2][4], alf[2][4], bfr[Cfg::NPAIR][4];
            // pass 1: Ah x Wh
            #pragma unroll
            for (int mi = 0; mi < 2; ++mi)
                ldsm4(af[mi][0], af[mi][1], af[mi][2], af[mi][3], sa + offA[mi][ks]);
            #pragma unroll
            for (int gi = 0; gi < Cfg::NPAIR; ++gi)
                ldsm4(bfr[gi][0], bfr[gi][1], bfr[gi][2], bfr[gi][3], sw + offB[gi][ks]);
            #pragma unroll
            for (int mi = 0; mi < 2; ++mi)
                #pragma unroll
                for (int g = 0; g < Cfg::NG; ++g)
                    mma_bf16(acc[mi][g], af[mi], &bfr[g >> 1][(g & 1) * 2]);
            // pass 2: Al x Wh
            #pragma unroll
            for (int mi = 0; mi < 2; ++mi)
                ldsm4(alf[mi][0], alf[mi][1], alf[mi][2], alf[mi][3],
                      sa + Cfg::TSZA + offA[mi][ks]);
            #pragma unroll
            for (int mi = 0; mi < 2; ++mi)
                #pragma unroll
                for (int g = 0; g < Cfg::NG; ++g)
                    mma_bf16(acc[mi][g], alf[mi], &bfr[g >> 1][(g & 1) * 2]);
            // pass 3: Ah x Wl
            #pragma unroll
            for (int gi = 0; gi < Cfg::NPAIR; ++gi)
                ldsm4(bfr[gi][0], bfr[gi][1], bfr[gi][2], bfr[gi][3],
                      sw + Cfg::TSZW + offB[gi][ks]);
            #pragma unroll
            for (int mi = 0; mi < 2; ++mi)
                #pragma unroll
                for (int g = 0; g < Cfg::NG; ++g)
                    mma_bf16(acc[mi][g], af[mi], &bfr[g >> 1][(g & 1) * 2]);
        }

        __syncthreads();
        if (t + NSTAGE < KTILES) load_stage(t + NSTAGE, buf);
    }

    // ---- epilogue (m16n8 C-frag layout) ----
    const int crow = lane >> 2;
    const int ccol = (lane & 3) * 2;
    #pragma unroll
    for (int mi = 0; mi < 2; ++mi) {
        #pragma unroll
        for (int g = 0; g < Cfg::NG; ++g) {
            const int col = n0 + wc * Cfg::NW + g * 8 + ccol;
            float b0 = BIAS ? bias[col]     : 0.f;
            float b1 = BIAS ? bias[col + 1] : 0.f;
            const int r0 = m0 + wr * 32 + mi * 16 + crow;
            float2 v0 = make_float2(acc[mi][g][0] + b0, acc[mi][g][1] + b1);
            float2 v1 = make_float2(acc[mi][g][2] + b0, acc[mi][g][3] + b1);
            *(float2*)(C + (size_t)r0 * Ndim + col)       = v0;
            *(float2*)(C + (size_t)(r0 + 8) * Ndim + col) = v1;
        }
    }
}

// ---------------------------------------------------------------------------
// Fused fp32 -> hi/lo bf16 split for all three tensors (one launch)
// ---------------------------------------------------------------------------
static constexpr int N4X = Mrows * Dd / 4;   // x
static constexpr int N4Q = QKVN  * Dd / 4;   // w_qkv
static constexpr int N4F = Dd    * Dd / 4;   // w_fc
static constexpr int N4ALL = N4X + N4Q + N4F;

__device__ __forceinline__ void split4(const float* __restrict__ s,
                                       bf16* __restrict__ h, bf16* __restrict__ l,
                                       int i) {
    float4 v = *(const float4*)(s + (size_t)i * 4);
    bf16 h0,h1,h2,h3,l0,l1,l2,l3;
    split_bf16(v.x,h0,l0); split_bf16(v.y,h1,l1);
    split_bf16(v.z,h2,l2); split_bf16(v.w,h3,l3);
    *(uint2*)(h + (size_t)i * 4) = pack4(h0,h1,h2,h3);
    *(uint2*)(l + (size_t)i * 4) = pack4(l0,l1,l2,l3);
}

__global__ void convert_all(const float* __restrict__ x,
                            const float* __restrict__ wq,
                            const float* __restrict__ wf,
                            bf16* __restrict__ xh, bf16* __restrict__ xl,
                            bf16* __restrict__ wqh, bf16* __restrict__ wql,
                            bf16* __restrict__ wfh, bf16* __restrict__ wfl)
{
    const int i = blockIdx.x * blockDim.x + threadIdx.x;
    if (i < N4X)               split4(x,  xh,  xl,  i);
    else if (i < N4X + N4Q)    split4(wq, wqh, wql, i - N4X);
    else if (i < N4ALL)        split4(wf, wfh, wfl, i - N4X - N4Q);
}

// ---------------------------------------------------------------------------
// Attention (faithful-reshape 16x16 head-mixing), one CTA per (b, r, j):
//   q_prep[b, n, h, dh] = q[b, h*256 + n/16, (n%16)*64 + dh]
// fp32 qkv in, hi/lo bf16 out.
// ---------------------------------------------------------------------------
__global__ __launch_bounds__(256)
void attn16_kernel(const float* __restrict__ qkv,
                   bf16* __restrict__ oh, bf16* __restrict__ ol)
{
    const int bxi = blockIdx.x;          // b*4096 + r*16 + j
    const int j = bxi & 15;
    const int r = (bxi >> 4) & 255;
    const int b = bxi >> 12;
    const int tid = threadIdx.x;
    const int hh = tid >> 4;
    const int lo = tid & 15;

    __shared__ float qs[16][64];
    __shared__ float ks[16][65];
    __shared__ float vs[16][64];
    __shared__ float ps[16][17];

    const size_t rowbase = ((size_t)b * 4096 + (size_t)hh * 256 + r) * 3072;
    const size_t outbase = ((size_t)b * 4096 + (size_t)hh * 256 + r) * 1024;
    const float scale = 0.125f;

    {
        const size_t c = (size_t)j * 64 + lo * 4;
        float4 q4 = *(const float4*)(qkv + rowbase + 0    + c);
        float4 k4 = *(const float4*)(qkv + rowbase + 1024 + c);
        float4 v4 = *(const float4*)(qkv + rowbase + 2048 + c);
        *(float4*)&qs[hh][lo * 4] = q4;
        ks[hh][lo * 4 + 0] = k4.x; ks[hh][lo * 4 + 1] = k4.y;
        ks[hh][lo * 4 + 2] = k4.z; ks[hh][lo * 4 + 3] = k4.w;
        *(float4*)&vs[hh][lo * 4] = v4;
    }
    __syncthreads();

    float s = 0.f;
    #pragma unroll
    for (int d = 0; d < 64; ++d) s = fmaf(qs[hh][d], ks[lo][d], s);
    s *= scale;

    float mx = s;
    #pragma unroll
    for (int off = 8; off; off >>= 1)
        mx = fmaxf(mx, __shfl_xor_sync(0xffffffffu, mx, off, 16));
    float e = __expf(s - mx);
    float sum = e;
    #pragma unroll
    for (int off = 8; off; off >>= 1)
        sum += __shfl_xor_sync(0xffffffffu, sum, off, 16);
    ps[hh][lo] = e / sum;
    __syncthreads();

    float4 o = make_float4(0.f, 0.f, 0.f, 0.f);
    #pragma unroll
    for (int g = 0; g < 16; ++g) {
        const float p = ps[hh][g];
        float4 v4 = *(const float4*)&vs[g][lo * 4];
        o.x = fmaf(p, v4.x, o.x); o.y = fmaf(p, v4.y, o.y);
        o.z = fmaf(p, v4.z, o.z); o.w = fmaf(p, v4.w, o.w);
    }
    bf16 h0,h1,h2,h3,l0,l1,l2,l3;
    split_bf16(o.x,h0,l0); split_bf16(o.y,h1,l1);
    split_bf16(o.z,h2,l2); split_bf16(o.w,h3,l3);
    *(uint2*)(oh + outbase + (size_t)j * 64 + lo * 4) = pack4(h0,h1,h2,h3);
    *(uint2*)(ol + outbase + (size_t)j * 64 + lo * 4) = pack4(l0,l1,l2,l3);
}

// ---------------------------------------------------------------------------
// Launch  (R11 configuration: BM=128 for both GEMMs — best known)
// ---------------------------------------------------------------------------
extern "C" void kernel_launch(void* const* d_in, const int* in_sizes, int n_in,
                              void* d_out, int out_size)
{
    const float* x     = (const float*)d_in[0];  // (4, 4096, 1024)
    const float* w_qkv = (const float*)d_in[1];  // (3072, 1024)
    const float* w_fc  = (const float*)d_in[2];  // (1024, 1024)
    const float* b_fc  = (const float*)d_in[3];  // (1024,)
    float* out = (float*)d_out;                  // (4, 4096, 1024)

    float *qkv_p; bf16 *xh_p, *xl_p, *ah_p, *al_p, *wqh_p, *wql_p, *wfh_p, *wfl_p;
    cudaGetSymbolAddress((void**)&qkv_p, g_qkv);
    cudaGetSymbolAddress((void**)&xh_p,  g_xh);  cudaGetSymbolAddress((void**)&xl_p,  g_xl);
    cudaGetSymbolAddress((void**)&ah_p,  g_ah);  cudaGetSymbolAddress((void**)&al_p,  g_al);
    cudaGetSymbolAddress((void**)&wqh_p, g_wqh); cudaGetSymbolAddress((void**)&wql_p, g_wql);
    cudaGetSymbolAddress((void**)&wfh_p, g_wfh); cudaGetSymbolAddress((void**)&wfl_p, g_wfl);

    constexpr int SMEM128 = GemmCfg<128>::SMEM;   // 98304 B
    cudaFuncSetAttribute(gemm_cp<128,false>, cudaFuncAttributeMaxDynamicSharedMemorySize, SMEM128);
    cudaFuncSetAttribute(gemm_cp<128,true>,  cudaFuncAttributeMaxDynamicSharedMemorySize, SMEM128);

    // 0) split inputs/weights into hi/lo bf16 (single fused launch)
    convert_all<<<(N4ALL + 255) / 256, 256>>>(x, w_qkv, w_fc,
                                              xh_p, xl_p, wqh_p, wql_p, wfh_p, wfl_p);

    // 1) qkv = x @ w_qkv^T  (M=16384, N=3072): 24 x 128 tiles (BM=128)
    gemm_cp<128,false><<<dim3(QKVN / 128, Mrows / 128), 256, SMEM128>>>(
        xh_p, xl_p, wqh_p, wql_p, nullptr, qkv_p, QKVN);

    // 2) 16x16 head-mix attention -> hi/lo bf16 (one CTA per (b,r,j))
    attn16_kernel<<<Bb * 256 * 16, 256>>>(qkv_p, ah_p, al_p);

    // 3) out = attn @ w_fc^T + b_fc  (M=16384, N=1024): 8 x 128 tiles
    gemm_cp<128,true><<<dim3(Dd / 128, Mrows / 128), 256, SMEM128>>>(
        ah_p, al_p, wfh_p, wfl_p, b_fc, out, Dd);
}

// round 14
// speedup vs baseline: 1.0975x; 1.0112x over previous
#include <cuda_runtime.h>
#include <cuda_bf16.h>
#include <cstddef>
#include <cstdint>

using bf16 = __nv_bfloat16;

// Problem constants
static constexpr int Bb    = 4;
static constexpr int Nn    = 4096;
static constexpr int Dd    = 1024;
static constexpr int Mrows = Bb * Nn;      // 16384
static constexpr int QKVN  = 3 * Dd;       // 3072
static constexpr int Kdim  = 1024;         // K of both GEMMs

// ---------------------------------------------------------------------------
// Scratch (__device__ globals; allocation-free rule)
// ---------------------------------------------------------------------------
__device__ float g_qkv[(size_t)Mrows * QKVN];          // fp32 qkv
__device__ bf16  g_xh [(size_t)Mrows * Dd], g_xl [(size_t)Mrows * Dd];
__device__ bf16  g_ah [(size_t)Mrows * Dd], g_al [(size_t)Mrows * Dd];
__device__ bf16  g_wqh[(size_t)QKVN  * Dd], g_wql[(size_t)QKVN  * Dd];
__device__ bf16  g_wfh[(size_t)Dd    * Dd], g_wfl[(size_t)Dd    * Dd];

// ---------------------------------------------------------------------------
// Helpers
// ---------------------------------------------------------------------------
__device__ __forceinline__ uint32_t smem_u32(const void* p) {
    return (uint32_t)__cvta_generic_to_shared(p);
}
__device__ __forceinline__ void ldsm4(uint32_t& r0, uint32_t& r1,
                                      uint32_t& r2, uint32_t& r3, uint32_t addr) {
    asm volatile("ldmatrix.sync.aligned.m8n8.x4.shared.b16 {%0,%1,%2,%3}, [%4];\n"
                 : "=r"(r0), "=r"(r1), "=r"(r2), "=r"(r3) : "r"(addr));
}
__device__ __forceinline__ void mma_bf16(float* c, const uint32_t* a, const uint32_t* b) {
    asm volatile(
        "mma.sync.aligned.m16n8k16.row.col.f32.bf16.bf16.f32 "
        "{%0,%1,%2,%3}, {%4,%5,%6,%7}, {%8,%9}, {%0,%1,%2,%3};\n"
        : "+f"(c[0]), "+f"(c[1]), "+f"(c[2]), "+f"(c[3])
        : "r"(a[0]), "r"(a[1]), "r"(a[2]), "r"(a[3]), "r"(b[0]), "r"(b[1]));
}
__device__ __forceinline__ void cp16(uint32_t dst, const void* src) {
    asm volatile("cp.async.cg.shared.global [%0], [%1], 16;" :: "r"(dst), "l"(src));
}
__device__ __forceinline__ void cp_commit() {
    asm volatile("cp.async.commit_group;" ::: "memory");
}
template <int N>
__device__ __forceinline__ void cp_wait() {
    asm volatile("cp.async.wait_group %0;" :: "n"(N) : "memory");
}
__device__ __forceinline__ void split_bf16(float v, bf16& h, bf16& l) {
    h = __float2bfloat16_rn(v);
    l = __float2bfloat16_rn(v - __bfloat162float(h));
}
__device__ __forceinline__ uint2 pack4(bf16 a, bf16 b, bf16 c, bf16 d) {
    uint2 r;
    uint16_t ua = *(uint16_t*)&a, ub = *(uint16_t*)&b;
    uint16_t uc = *(uint16_t*)&c, ud = *(uint16_t*)&d;
    r.x = (uint32_t)ua | ((uint32_t)ub << 16);
    r.y = (uint32_t)uc | ((uint32_t)ud << 16);
    return r;
}

// ---------------------------------------------------------------------------
// bf16x3 tensor-core GEMM (NT), cp.async 3-stage pipeline  (R6/R11 — best).
//   C[m][n] = sum_k A[m][k]*W[n][k] (+bias),  C ~= Ah*Wh + Al*Wh + Ah*Wl
// Inputs pre-split hi/lo bf16, K-major, K=1024. CTA 128x128, BK=32,
// 8 warps (4m x 2n), warp tile 32m x 64n, m16n8k16.
// smem per stage: [Ah | Al | Wh | Wl], each 128 rows x 64 B,
// XOR swizzle: chunk' = chunk ^ ((row>>1)&3)  (16 B chunks, 4 per row).
// ---------------------------------------------------------------------------
static constexpr int BK      = 32;
static constexpr int KTILES  = Kdim / BK;        // 32
static constexpr int TSZ     = 128 * 64;          // 8192 B per array tile
static constexpr int STAGE   = 4 * TSZ;           // 32768 B
static constexpr int NSTAGE  = 3;
static constexpr int SMEM_TOTAL = NSTAGE * STAGE; // 98304 B

template <bool BIAS>
__global__ __launch_bounds__(256, 2)
void gemm_cp(const bf16* __restrict__ Ah, const bf16* __restrict__ Al,
             const bf16* __restrict__ Wh, const bf16* __restrict__ Wl,
             const float* __restrict__ bias, float* __restrict__ C, int Ndim)
{
    extern __shared__ char smem[];
    const uint32_t smem_base = smem_u32(smem);
    const int tid  = threadIdx.x;
    const int wid  = tid >> 5;
    const int lane = tid & 31;
    const int wr   = wid & 3;           // m offset wr*32
    const int wc   = wid >> 2;          // n offset wc*64
    const int m0   = blockIdx.y * 128;
    const int n0   = blockIdx.x * 128;

    const bf16* src[4] = { Ah + (size_t)m0 * Kdim, Al + (size_t)m0 * Kdim,
                           Wh + (size_t)n0 * Kdim, Wl + (size_t)n0 * Kdim };

    // ---- cp.async mapping (per thread: 8 chunks of 16 B per stage) ----
    auto load_stage = [&](int t, int buf) {
        const int k0 = t * BK;
        const uint32_t sb = smem_base + buf * STAGE;
        #pragma unroll
        for (int i = 0; i < 8; ++i) {
            const int idx = tid + i * 256;
            const int arr = idx >> 9;
            const int id2 = idx & 511;
            const int row = id2 >> 2;
            const int ch  = id2 & 3;
            const uint32_t dst = sb + arr * TSZ + row * 64 +
                                 ((ch ^ ((row >> 1) & 3)) << 4);
            cp16(dst, src[arr] + (size_t)row * Kdim + k0 + ch * 8);
        }
        cp_commit();
    };

    // ---- ldmatrix offsets (within stage), per mi/gi and k-step ----
    const int tq   = lane >> 3;
    const int arow = (lane & 7) + (tq & 1) * 8;
    const int ach  = tq >> 1;
    const int brow = (tq >> 1) * 8 + (lane & 7);
    const int bch  = tq & 1;

    uint32_t offA[2][2], offB[4][2];
    #pragma unroll
    for (int mi = 0; mi < 2; ++mi) {
        const int row = wr * 32 + mi * 16 + arow;
        #pragma unroll
        for (int ks = 0; ks < 2; ++ks) {
            const int ch = ach + ks * 2;
            offA[mi][ks] = row * 64 + (((ch ^ ((row >> 1) & 3))) << 4);
        }
    }
    #pragma unroll
    for (int gi = 0; gi < 4; ++gi) {
        const int row = wc * 64 + gi * 16 + brow;
        #pragma unroll
        for (int ks = 0; ks < 2; ++ks) {
            const int ch = bch + ks * 2;
            offB[gi][ks] = row * 64 + (((ch ^ ((row >> 1) & 3))) << 4);
        }
    }

    float acc[2][8][4];
    #pragma unroll
    for (int i = 0; i < 2; ++i)
        #pragma unroll
        for (int j = 0; j < 8; ++j)
            #pragma unroll
            for (int e = 0; e < 4; ++e) acc[i][j][e] = 0.f;

    // ---- prologue: fill the pipeline ----
    load_stage(0, 0);
    load_stage(1, 1);
    load_stage(2, 2);

    for (int t = 0; t < KTILES; ++t) {
        cp_wait<2>();              // stage t landed
        __syncthreads();

        const int buf = t % NSTAGE;
        const uint32_t sa = smem_base + buf * STAGE;            // Ah base
        const uint32_t sw = sa + 2 * TSZ;                       // Wh base

        #pragma unroll
        for (int ks = 0; ks < 2; ++ks) {
            uint32_t af[2][4], alf[2][4], bfr[4][4];
            // pass 1: Ah x Wh
            #pragma unroll
            for (int mi = 0; mi < 2; ++mi)
                ldsm4(af[mi][0], af[mi][1], af[mi][2], af[mi][3], sa + offA[mi][ks]);
            #pragma unroll
            for (int gi = 0; gi < 4; ++gi)
                ldsm4(bfr[gi][0], bfr[gi][1], bfr[gi][2], bfr[gi][3], sw + offB[gi][ks]);
            #pragma unroll
            for (int mi = 0; mi < 2; ++mi)
                #pragma unroll
                for (int g = 0; g < 8; ++g)
                    mma_bf16(acc[mi][g], af[mi], &bfr[g >> 1][(g & 1) * 2]);
            // pass 2: Al x Wh
            #pragma unroll
            for (int mi = 0; mi < 2; ++mi)
                ldsm4(alf[mi][0], alf[mi][1], alf[mi][2], alf[mi][3],
                      sa + TSZ + offA[mi][ks]);
            #pragma unroll
            for (int mi = 0; mi < 2; ++mi)
                #pragma unroll
                for (int g = 0; g < 8; ++g)
                    mma_bf16(acc[mi][g], alf[mi], &bfr[g >> 1][(g & 1) * 2]);
            // pass 3: Ah x Wl
            #pragma unroll
            for (int gi = 0; gi < 4; ++gi)
                ldsm4(bfr[gi][0], bfr[gi][1], bfr[gi][2], bfr[gi][3],
                      sw + TSZ + offB[gi][ks]);
            #pragma unroll
            for (int mi = 0; mi < 2; ++mi)
                #pragma unroll
                for (int g = 0; g < 8; ++g)
                    mma_bf16(acc[mi][g], af[mi], &bfr[g >> 1][(g & 1) * 2]);
        }

        __syncthreads();
        if (t + NSTAGE < KTILES) load_stage(t + NSTAGE, buf);
    }

    // ---- epilogue (m16n8 C-frag layout) ----
    const int crow = lane >> 2;
    const int ccol = (lane & 3) * 2;
    #pragma unroll
    for (int mi = 0; mi < 2; ++mi) {
        #pragma unroll
        for (int g = 0; g < 8; ++g) {
            const int col = n0 + wc * 64 + g * 8 + ccol;
            float b0 = BIAS ? bias[col]     : 0.f;
            float b1 = BIAS ? bias[col + 1] : 0.f;
            const int r0 = m0 + wr * 32 + mi * 16 + crow;
            float2 v0 = make_float2(acc[mi][g][0] + b0, acc[mi][g][1] + b1);
            float2 v1 = make_float2(acc[mi][g][2] + b0, acc[mi][g][3] + b1);
            *(float2*)(C + (size_t)r0 * Ndim + col)       = v0;
            *(float2*)(C + (size_t)(r0 + 8) * Ndim + col) = v1;
        }
    }
}

// ---------------------------------------------------------------------------
// Fused fp32 -> hi/lo bf16 split for all three tensors (one launch)
// ---------------------------------------------------------------------------
static constexpr int N4X = Mrows * Dd / 4;   // x
static constexpr int N4Q = QKVN  * Dd / 4;   // w_qkv
static constexpr int N4F = Dd    * Dd / 4;   // w_fc
static constexpr int N4ALL = N4X + N4Q + N4F;

__device__ __forceinline__ void split4(const float* __restrict__ s,
                                       bf16* __restrict__ h, bf16* __restrict__ l,
                                       int i) {
    float4 v = *(const float4*)(s + (size_t)i * 4);
    bf16 h0,h1,h2,h3,l0,l1,l2,l3;
    split_bf16(v.x,h0,l0); split_bf16(v.y,h1,l1);
    split_bf16(v.z,h2,l2); split_bf16(v.w,h3,l3);
    *(uint2*)(h + (size_t)i * 4) = pack4(h0,h1,h2,h3);
    *(uint2*)(l + (size_t)i * 4) = pack4(l0,l1,l2,l3);
}

__global__ void convert_all(const float* __restrict__ x,
                            const float* __restrict__ wq,
                            const float* __restrict__ wf,
                            bf16* __restrict__ xh, bf16* __restrict__ xl,
                            bf16* __restrict__ wqh, bf16* __restrict__ wql,
                            bf16* __restrict__ wfh, bf16* __restrict__ wfl)
{
    const int i = blockIdx.x * blockDim.x + threadIdx.x;
    if (i < N4X)               split4(x,  xh,  xl,  i);
    else if (i < N4X + N4Q)    split4(wq, wqh, wql, i - N4X);
    else if (i < N4ALL)        split4(wf, wfh, wfl, i - N4X - N4Q);
}

// ---------------------------------------------------------------------------
// Attention (faithful-reshape 16x16 head-mixing), one CTA per (b, r, j):
//   q_prep[b, n, h, dh] = q[b, h*256 + n/16, (n%16)*64 + dh]
// fp32 qkv in, hi/lo bf16 out.
// ---------------------------------------------------------------------------
__global__ __launch_bounds__(256)
void attn16_kernel(const float* __restrict__ qkv,
                   bf16* __restrict__ oh, bf16* __restrict__ ol)
{
    const int bxi = blockIdx.x;          // b*4096 + r*16 + j
    const int j = bxi & 15;
    const int r = (bxi >> 4) & 255;
    const int b = bxi >> 12;
    const int tid = threadIdx.x;
    const int hh = tid >> 4;
    const int lo = tid & 15;

    __shared__ float qs[16][64];
    __shared__ float ks[16][65];
    __shared__ float vs[16][64];
    __shared__ float ps[16][17];

    const size_t rowbase = ((size_t)b * 4096 + (size_t)hh * 256 + r) * 3072;
    const size_t outbase = ((size_t)b * 4096 + (size_t)hh * 256 + r) * 1024;
    const float scale = 0.125f;

    {
        const size_t c = (size_t)j * 64 + lo * 4;
        float4 q4 = *(const float4*)(qkv + rowbase + 0    + c);
        float4 k4 = *(const float4*)(qkv + rowbase + 1024 + c);
        float4 v4 = *(const float4*)(qkv + rowbase + 2048 + c);
        *(float4*)&qs[hh][lo * 4] = q4;
        ks[hh][lo * 4 + 0] = k4.x; ks[hh][lo * 4 + 1] = k4.y;
        ks[hh][lo * 4 + 2] = k4.z; ks[hh][lo * 4 + 3] = k4.w;
        *(float4*)&vs[hh][lo * 4] = v4;
    }
    __syncthreads();

    float s = 0.f;
    #pragma unroll
    for (int d = 0; d < 64; ++d) s = fmaf(qs[hh][d], ks[lo][d], s);
    s *= scale;

    float mx = s;
    #pragma unroll
    for (int off = 8; off; off >>= 1)
        mx = fmaxf(mx, __shfl_xor_sync(0xffffffffu, mx, off, 16));
    float e = __expf(s - mx);
    float sum = e;
    #pragma unroll
    for (int off = 8; off; off >>= 1)
        sum += __shfl_xor_sync(0xffffffffu, sum, off, 16);
    ps[hh][lo] = e / sum;
    __syncthreads();

    float4 o = make_float4(0.f, 0.f, 0.f, 0.f);
    #pragma unroll
    for (int g = 0; g < 16; ++g) {
        const float p = ps[hh][g];
        float4 v4 = *(const float4*)&vs[g][lo * 4];
        o.x = fmaf(p, v4.x, o.x); o.y = fmaf(p, v4.y, o.y);
        o.z = fmaf(p, v4.z, o.z); o.w = fmaf(p, v4.w, o.w);
    }
    bf16 h0,h1,h2,h3,l0,l1,l2,l3;
    split_bf16(o.x,h0,l0); split_bf16(o.y,h1,l1);
    split_bf16(o.z,h2,l2); split_bf16(o.w,h3,l3);
    *(uint2*)(oh + outbase + (size_t)j * 64 + lo * 4) = pack4(h0,h1,h2,h3);
    *(uint2*)(ol + outbase + (size_t)j * 64 + lo * 4) = pack4(l0,l1,l2,l3);
}

// ---------------------------------------------------------------------------
// Launch  (exact R11 configuration — best measured: 1121.6 us)
// ---------------------------------------------------------------------------
extern "C" void kernel_launch(void* const* d_in, const int* in_sizes, int n_in,
                              void* d_out, int out_size)
{
    const float* x     = (const float*)d_in[0];  // (4, 4096, 1024)
    const float* w_qkv = (const float*)d_in[1];  // (3072, 1024)
    const float* w_fc  = (const float*)d_in[2];  // (1024, 1024)
    const float* b_fc  = (const float*)d_in[3];  // (1024,)
    float* out = (float*)d_out;                  // (4, 4096, 1024)

    float *qkv_p; bf16 *xh_p, *xl_p, *ah_p, *al_p, *wqh_p, *wql_p, *wfh_p, *wfl_p;
    cudaGetSymbolAddress((void**)&qkv_p, g_qkv);
    cudaGetSymbolAddress((void**)&xh_p,  g_xh);  cudaGetSymbolAddress((void**)&xl_p,  g_xl);
    cudaGetSymbolAddress((void**)&ah_p,  g_ah);  cudaGetSymbolAddress((void**)&al_p,  g_al);
    cudaGetSymbolAddress((void**)&wqh_p, g_wqh); cudaGetSymbolAddress((void**)&wql_p, g_wql);
    cudaGetSymbolAddress((void**)&wfh_p, g_wfh); cudaGetSymbolAddress((void**)&wfl_p, g_wfl);

    cudaFuncSetAttribute(gemm_cp<false>, cudaFuncAttributeMaxDynamicSharedMemorySize, SMEM_TOTAL);
    cudaFuncSetAttribute(gemm_cp<true>,  cudaFuncAttributeMaxDynamicSharedMemorySize, SMEM_TOTAL);

    // 0) split inputs/weights into hi/lo bf16 (single fused launch)
    convert_all<<<(N4ALL + 255) / 256, 256>>>(x, w_qkv, w_fc,
                                              xh_p, xl_p, wqh_p, wql_p, wfh_p, wfl_p);

    // 1) qkv = x @ w_qkv^T  (fp32 out, M=16384, N=3072)
    gemm_cp<false><<<dim3(QKVN / 128, Mrows / 128), 256, SMEM_TOTAL>>>(
        xh_p, xl_p, wqh_p, wql_p, nullptr, qkv_p, QKVN);

    // 2) 16x16 head-mix attention -> hi/lo bf16 (one CTA per (b,r,j))
    attn16_kernel<<<Bb * 256 * 16, 256>>>(qkv_p, ah_p, al_p);

    // 3) out = attn @ w_fc^T + b_fc  (M=16384, N=1024)
    gemm_cp<true><<<dim3(Dd / 128, Mrows / 128), 256, SMEM_TOTAL>>>(
        ah_p, al_p, wfh_p, wfl_p, b_fc, out, Dd);
}

// round 15
// speedup vs baseline: 1.5315x; 1.3954x over previous
#include <cuda_runtime.h>
#include <cuda_fp16.h>
#include <cstddef>
#include <cstdint>

using f16 = __half;

// Problem constants
static constexpr int Bb    = 4;
static constexpr int Nn    = 4096;
static constexpr int Dd    = 1024;
static constexpr int Mrows = Bb * Nn;      // 16384
static constexpr int QKVN  = 3 * Dd;       // 3072
static constexpr int Kdim  = 1024;         // K of both GEMMs

// ---------------------------------------------------------------------------
// Scratch (__device__ globals; allocation-free rule)
// ---------------------------------------------------------------------------
__device__ float g_qkv[(size_t)Mrows * QKVN];          // fp32 qkv
__device__ f16   g_xh [(size_t)Mrows * Dd], g_xl [(size_t)Mrows * Dd];
__device__ f16   g_ah [(size_t)Mrows * Dd], g_al [(size_t)Mrows * Dd];
__device__ f16   g_wq16[(size_t)QKVN * Dd];            // fp16(w_qkv)
__device__ f16   g_wf16[(size_t)Dd   * Dd];            // fp16(w_fc)

// ---------------------------------------------------------------------------
// Helpers
// ---------------------------------------------------------------------------
__device__ __forceinline__ uint32_t smem_u32(const void* p) {
    return (uint32_t)__cvta_generic_to_shared(p);
}
__device__ __forceinline__ void ldsm4(uint32_t& r0, uint32_t& r1,
                                      uint32_t& r2, uint32_t& r3, uint32_t addr) {
    asm volatile("ldmatrix.sync.aligned.m8n8.x4.shared.b16 {%0,%1,%2,%3}, [%4];\n"
                 : "=r"(r0), "=r"(r1), "=r"(r2), "=r"(r3) : "r"(addr));
}
__device__ __forceinline__ void mma_f16(float* c, const uint32_t* a, const uint32_t* b) {
    asm volatile(
        "mma.sync.aligned.m16n8k16.row.col.f32.f16.f16.f32 "
        "{%0,%1,%2,%3}, {%4,%5,%6,%7}, {%8,%9}, {%0,%1,%2,%3};\n"
        : "+f"(c[0]), "+f"(c[1]), "+f"(c[2]), "+f"(c[3])
        : "r"(a[0]), "r"(a[1]), "r"(a[2]), "r"(a[3]), "r"(b[0]), "r"(b[1]));
}
__device__ __forceinline__ void cp16(uint32_t dst, const void* src) {
    asm volatile("cp.async.cg.shared.global [%0], [%1], 16;" :: "r"(dst), "l"(src));
}
__device__ __forceinline__ void cp_commit() {
    asm volatile("cp.async.commit_group;" ::: "memory");
}
template <int N>
__device__ __forceinline__ void cp_wait() {
    asm volatile("cp.async.wait_group %0;" :: "n"(N) : "memory");
}
__device__ __forceinline__ void split_f16(float v, f16& h, f16& l) {
    h = __float2half_rn(v);
    l = __float2half_rn(v - __half2float(h));
}
__device__ __forceinline__ uint2 pack4h(f16 a, f16 b, f16 c, f16 d) {
    uint2 r;
    uint16_t ua = *(uint16_t*)&a, ub = *(uint16_t*)&b;
    uint16_t uc = *(uint16_t*)&c, ud = *(uint16_t*)&d;
    r.x = (uint32_t)ua | ((uint32_t)ub << 16);
    r.y = (uint32_t)uc | ((uint32_t)ud << 16);
    return r;
}

// ---------------------------------------------------------------------------
// fp16x2 tensor-core GEMM (NT), cp.async 3-stage pipeline (R6 structure).
//   C[m][n] = sum_k A[m][k]*W[n][k] (+bias)
//   A pre-split fp16 hi/lo (A = Ah + Al exactly to ~2^-22), W = fp16(W).
//   C = Ah*W16 + Al*W16  -> dominant error = W rounding ~2.8e-4 (norm-rel).
// CTA 128x128, BK=32, 8 warps (4m x 2n), warp tile 32m x 64n, m16n8k16.
// smem per stage: [Ah | Al | W], each 128 rows x 64 B,
// XOR swizzle: chunk' = chunk ^ ((row>>1)&3)  (16 B chunks, 4 per row).
// ---------------------------------------------------------------------------
static constexpr int BK      = 32;
static constexpr int KTILES  = Kdim / BK;        // 32
static constexpr int TSZ     = 128 * 64;          // 8192 B per array tile
static constexpr int STAGE   = 3 * TSZ;           // 24576 B
static constexpr int NSTAGE  = 3;
static constexpr int SMEM_TOTAL = NSTAGE * STAGE; // 73728 B

template <bool BIAS>
__global__ __launch_bounds__(256, 2)
void gemm_cp(const f16* __restrict__ Ah, const f16* __restrict__ Al,
             const f16* __restrict__ W16,
             const float* __restrict__ bias, float* __restrict__ C, int Ndim)
{
    extern __shared__ char smem[];
    const uint32_t smem_base = smem_u32(smem);
    const int tid  = threadIdx.x;
    const int wid  = tid >> 5;
    const int lane = tid & 31;
    const int wr   = wid & 3;           // m offset wr*32
    const int wc   = wid >> 2;          // n offset wc*64
    const int m0   = blockIdx.y * 128;
    const int n0   = blockIdx.x * 128;

    const f16* src[3] = { Ah + (size_t)m0 * Kdim, Al + (size_t)m0 * Kdim,
                          W16 + (size_t)n0 * Kdim };

    // ---- cp.async mapping (per thread: 6 chunks of 16 B per stage) ----
    auto load_stage = [&](int t, int buf) {
        const int k0 = t * BK;
        const uint32_t sb = smem_base + buf * STAGE;
        #pragma unroll
        for (int i = 0; i < 6; ++i) {
            const int idx = tid + i * 256;        // 0..1535
            const int arr = idx >> 9;             // 0,1,2
            const int id2 = idx & 511;
            const int row = id2 >> 2;
            const int ch  = id2 & 3;
            const uint32_t dst = sb + arr * TSZ + row * 64 +
                                 ((ch ^ ((row >> 1) & 3)) << 4);
            cp16(dst, src[arr] + (size_t)row * Kdim + k0 + ch * 8);
        }
        cp_commit();
    };

    // ---- ldmatrix offsets (within stage), per mi/gi and k-step ----
    const int tq   = lane >> 3;
    const int arow = (lane & 7) + (tq & 1) * 8;
    const int ach  = tq >> 1;
    const int brow = (tq >> 1) * 8 + (lane & 7);
    const int bch  = tq & 1;

    uint32_t offA[2][2], offB[4][2];
    #pragma unroll
    for (int mi = 0; mi < 2; ++mi) {
        const int row = wr * 32 + mi * 16 + arow;
        #pragma unroll
        for (int ks = 0; ks < 2; ++ks) {
            const int ch = ach + ks * 2;
            offA[mi][ks] = row * 64 + (((ch ^ ((row >> 1) & 3))) << 4);
        }
    }
    #pragma unroll
    for (int gi = 0; gi < 4; ++gi) {
        const int row = wc * 64 + gi * 16 + brow;
        #pragma unroll
        for (int ks = 0; ks < 2; ++ks) {
            const int ch = bch + ks * 2;
            offB[gi][ks] = row * 64 + (((ch ^ ((row >> 1) & 3))) << 4);
        }
    }

    float acc[2][8][4];
    #pragma unroll
    for (int i = 0; i < 2; ++i)
        #pragma unroll
        for (int j = 0; j < 8; ++j)
            #pragma unroll
            for (int e = 0; e < 4; ++e) acc[i][j][e] = 0.f;

    // ---- prologue: fill the pipeline ----
    load_stage(0, 0);
    load_stage(1, 1);
    load_stage(2, 2);

    for (int t = 0; t < KTILES; ++t) {
        cp_wait<2>();              // stage t landed
        __syncthreads();

        const int buf = t % NSTAGE;
        const uint32_t sa = smem_base + buf * STAGE;            // Ah base
        const uint32_t sw = sa + 2 * TSZ;                       // W base

        #pragma unroll
        for (int ks = 0; ks < 2; ++ks) {
            uint32_t af[2][4], alf[2][4], bfr[4][4];
            // hoist all ldsm: af, alf, W frags in flight together
            #pragma unroll
            for (int mi = 0; mi < 2; ++mi)
                ldsm4(af[mi][0], af[mi][1], af[mi][2], af[mi][3], sa + offA[mi][ks]);
            #pragma unroll
            for (int mi = 0; mi < 2; ++mi)
                ldsm4(alf[mi][0], alf[mi][1], alf[mi][2], alf[mi][3],
                      sa + TSZ + offA[mi][ks]);
            #pragma unroll
            for (int gi = 0; gi < 4; ++gi)
                ldsm4(bfr[gi][0], bfr[gi][1], bfr[gi][2], bfr[gi][3], sw + offB[gi][ks]);
            // pass 1: Ah x W
            #pragma unroll
            for (int mi = 0; mi < 2; ++mi)
                #pragma unroll
                for (int g = 0; g < 8; ++g)
                    mma_f16(acc[mi][g], af[mi], &bfr[g >> 1][(g & 1) * 2]);
            // pass 2: Al x W
            #pragma unroll
            for (int mi = 0; mi < 2; ++mi)
                #pragma unroll
                for (int g = 0; g < 8; ++g)
                    mma_f16(acc[mi][g], alf[mi], &bfr[g >> 1][(g & 1) * 2]);
        }

        __syncthreads();
        if (t + NSTAGE < KTILES) load_stage(t + NSTAGE, buf);
    }

    // ---- epilogue (m16n8 C-frag layout) ----
    const int crow = lane >> 2;
    const int ccol = (lane & 3) * 2;
    #pragma unroll
    for (int mi = 0; mi < 2; ++mi) {
        #pragma unroll
        for (int g = 0; g < 8; ++g) {
            const int col = n0 + wc * 64 + g * 8 + ccol;
            float b0 = BIAS ? bias[col]     : 0.f;
            float b1 = BIAS ? bias[col + 1] : 0.f;
            const int r0 = m0 + wr * 32 + mi * 16 + crow;
            float2 v0 = make_float2(acc[mi][g][0] + b0, acc[mi][g][1] + b1);
            float2 v1 = make_float2(acc[mi][g][2] + b0, acc[mi][g][3] + b1);
            *(float2*)(C + (size_t)r0 * Ndim + col)       = v0;
            *(float2*)(C + (size_t)(r0 + 8) * Ndim + col) = v1;
        }
    }
}

// ---------------------------------------------------------------------------
// Fused converts: x -> fp16 hi/lo; w_qkv, w_fc -> single fp16
// ---------------------------------------------------------------------------
static constexpr int N4X = Mrows * Dd / 4;   // x
static constexpr int N4Q = QKVN  * Dd / 4;   // w_qkv
static constexpr int N4F = Dd    * Dd / 4;   // w_fc
static constexpr int N4ALL = N4X + N4Q + N4F;

__device__ __forceinline__ void split4h(const float* __restrict__ s,
                                        f16* __restrict__ h, f16* __restrict__ l,
                                        int i) {
    float4 v = *(const float4*)(s + (size_t)i * 4);
    f16 h0,h1,h2,h3,l0,l1,l2,l3;
    split_f16(v.x,h0,l0); split_f16(v.y,h1,l1);
    split_f16(v.z,h2,l2); split_f16(v.w,h3,l3);
    *(uint2*)(h + (size_t)i * 4) = pack4h(h0,h1,h2,h3);
    *(uint2*)(l + (size_t)i * 4) = pack4h(l0,l1,l2,l3);
}
__device__ __forceinline__ void conv4h(const float* __restrict__ s,
                                       f16* __restrict__ h, int i) {
    float4 v = *(const float4*)(s + (size_t)i * 4);
    *(uint2*)(h + (size_t)i * 4) = pack4h(__float2half_rn(v.x), __float2half_rn(v.y),
                                          __float2half_rn(v.z), __float2half_rn(v.w));
}

__global__ void convert_all(const float* __restrict__ x,
                            const float* __restrict__ wq,
                            const float* __restrict__ wf,
                            f16* __restrict__ xh, f16* __restrict__ xl,
                            f16* __restrict__ wq16, f16* __restrict__ wf16)
{
    const int i = blockIdx.x * blockDim.x + threadIdx.x;
    if (i < N4X)               split4h(x, xh, xl, i);
    else if (i < N4X + N4Q)    conv4h(wq, wq16, i - N4X);
    else if (i < N4ALL)        conv4h(wf, wf16, i - N4X - N4Q);
}

// ---------------------------------------------------------------------------
// Attention (faithful-reshape 16x16 head-mixing), one CTA per (b, r, j):
//   q_prep[b, n, h, dh] = q[b, h*256 + n/16, (n%16)*64 + dh]
// fp32 qkv in, fp16 hi/lo out (feeds FC GEMM A-side).
// ---------------------------------------------------------------------------
__global__ __launch_bounds__(256)
void attn16_kernel(const float* __restrict__ qkv,
                   f16* __restrict__ oh, f16* __restrict__ ol)
{
    const int bxi = blockIdx.x;          // b*4096 + r*16 + j
    const int j = bxi & 15;
    const int r = (bxi >> 4) & 255;
    const int b = bxi >> 12;
    const int tid = threadIdx.x;
    const int hh = tid >> 4;
    const int lo = tid & 15;

    __shared__ float qs[16][64];
    __shared__ float ks[16][65];
    __shared__ float vs[16][64];
    __shared__ float ps[16][17];

    const size_t rowbase = ((size_t)b * 4096 + (size_t)hh * 256 + r) * 3072;
    const size_t outbase = ((size_t)b * 4096 + (size_t)hh * 256 + r) * 1024;
    const float scale = 0.125f;

    {
        const size_t c = (size_t)j * 64 + lo * 4;
        float4 q4 = *(const float4*)(qkv + rowbase + 0    + c);
        float4 k4 = *(const float4*)(qkv + rowbase + 1024 + c);
        float4 v4 = *(const float4*)(qkv + rowbase + 2048 + c);
        *(float4*)&qs[hh][lo * 4] = q4;
        ks[hh][lo * 4 + 0] = k4.x; ks[hh][lo * 4 + 1] = k4.y;
        ks[hh][lo * 4 + 2] = k4.z; ks[hh][lo * 4 + 3] = k4.w;
        *(float4*)&vs[hh][lo * 4] = v4;
    }
    __syncthreads();

    float s = 0.f;
    #pragma unroll
    for (int d = 0; d < 64; ++d) s = fmaf(qs[hh][d], ks[lo][d], s);
    s *= scale;

    float mx = s;
    #pragma unroll
    for (int off = 8; off; off >>= 1)
        mx = fmaxf(mx, __shfl_xor_sync(0xffffffffu, mx, off, 16));
    float e = __expf(s - mx);
    float sum = e;
    #pragma unroll
    for (int off = 8; off; off >>= 1)
        sum += __shfl_xor_sync(0xffffffffu, sum, off, 16);
    ps[hh][lo] = e / sum;
    __syncthreads();

    float4 o = make_float4(0.f, 0.f, 0.f, 0.f);
    #pragma unroll
    for (int g = 0; g < 16; ++g) {
        const float p = ps[hh][g];
        float4 v4 = *(const float4*)&vs[g][lo * 4];
        o.x = fmaf(p, v4.x, o.x); o.y = fmaf(p, v4.y, o.y);
        o.z = fmaf(p, v4.z, o.z); o.w = fmaf(p, v4.w, o.w);
    }
    f16 h0,h1,h2,h3,l0,l1,l2,l3;
    split_f16(o.x,h0,l0); split_f16(o.y,h1,l1);
    split_f16(o.z,h2,l2); split_f16(o.w,h3,l3);
    *(uint2*)(oh + outbase + (size_t)j * 64 + lo * 4) = pack4h(h0,h1,h2,h3);
    *(uint2*)(ol + outbase + (size_t)j * 64 + lo * 4) = pack4h(l0,l1,l2,l3);
}

// ---------------------------------------------------------------------------
// Launch
// ---------------------------------------------------------------------------
extern "C" void kernel_launch(void* const* d_in, const int* in_sizes, int n_in,
                              void* d_out, int out_size)
{
    const float* x     = (const float*)d_in[0];  // (4, 4096, 1024)
    const float* w_qkv = (const float*)d_in[1];  // (3072, 1024)
    const float* w_fc  = (const float*)d_in[2];  // (1024, 1024)
    const float* b_fc  = (const float*)d_in[3];  // (1024,)
    float* out = (float*)d_out;                  // (4, 4096, 1024)

    float *qkv_p; f16 *xh_p, *xl_p, *ah_p, *al_p, *wq_p, *wf_p;
    cudaGetSymbolAddress((void**)&qkv_p, g_qkv);
    cudaGetSymbolAddress((void**)&xh_p,  g_xh);  cudaGetSymbolAddress((void**)&xl_p, g_xl);
    cudaGetSymbolAddress((void**)&ah_p,  g_ah);  cudaGetSymbolAddress((void**)&al_p, g_al);
    cudaGetSymbolAddress((void**)&wq_p,  g_wq16);
    cudaGetSymbolAddress((void**)&wf_p,  g_wf16);

    cudaFuncSetAttribute(gemm_cp<false>, cudaFuncAttributeMaxDynamicSharedMemorySize, SMEM_TOTAL);
    cudaFuncSetAttribute(gemm_cp<true>,  cudaFuncAttributeMaxDynamicSharedMemorySize, SMEM_TOTAL);

    // 0) converts: x -> fp16 hi/lo; weights -> fp16 (single fused launch)
    convert_all<<<(N4ALL + 255) / 256, 256>>>(x, w_qkv, w_fc,
                                              xh_p, xl_p, wq_p, wf_p);

    // 1) qkv = x @ w_qkv^T  (fp32 out, M=16384, N=3072)
    gemm_cp<false><<<dim3(QKVN / 128, Mrows / 128), 256, SMEM_TOTAL>>>(
        xh_p, xl_p, wq_p, nullptr, qkv_p, QKVN);

    // 2) 16x16 head-mix attention -> fp16 hi/lo (one CTA per (b,r,j))
    attn16_kernel<<<Bb * 256 * 16, 256>>>(qkv_p, ah_p, al_p);

    // 3) out = attn @ w_fc^T + b_fc  (M=16384, N=1024)
    gemm_cp<true><<<dim3(Dd / 128, Mrows / 128), 256, SMEM_TOTAL>>>(
        ah_p, al_p, wf_p, b_fc, out, Dd);
}

// round 16
// speedup vs baseline: 2.2710x; 1.4828x over previous
#include <cuda_runtime.h>
#include <cuda_fp16.h>
#include <cstddef>
#include <cstdint>

using f16 = __half;

// Problem constants
static constexpr int Bb    = 4;
static constexpr int Nn    = 4096;
static constexpr int Dd    = 1024;
static constexpr int Mrows = Bb * Nn;      // 16384
static constexpr int QKVN  = 3 * Dd;       // 3072
static constexpr int Kdim  = 1024;         // K of both GEMMs

// ---------------------------------------------------------------------------
// Scratch (__device__ globals; allocation-free rule)
// ---------------------------------------------------------------------------
__device__ float g_qkv[(size_t)Mrows * QKVN];          // fp32 qkv
__device__ f16   g_x16 [(size_t)Mrows * Dd];           // fp16(x)
__device__ f16   g_a16 [(size_t)Mrows * Dd];           // fp16(attn out)
__device__ f16   g_wq16[(size_t)QKVN * Dd];            // fp16(w_qkv)
__device__ f16   g_wf16[(size_t)Dd   * Dd];            // fp16(w_fc)

// ---------------------------------------------------------------------------
// Helpers
// ---------------------------------------------------------------------------
__device__ __forceinline__ uint32_t smem_u32(const void* p) {
    return (uint32_t)__cvta_generic_to_shared(p);
}
__device__ __forceinline__ void ldsm4(uint32_t& r0, uint32_t& r1,
                                      uint32_t& r2, uint32_t& r3, uint32_t addr) {
    asm volatile("ldmatrix.sync.aligned.m8n8.x4.shared.b16 {%0,%1,%2,%3}, [%4];\n"
                 : "=r"(r0), "=r"(r1), "=r"(r2), "=r"(r3) : "r"(addr));
}
__device__ __forceinline__ void mma_f16(float* c, const uint32_t* a, const uint32_t* b) {
    asm volatile(
        "mma.sync.aligned.m16n8k16.row.col.f32.f16.f16.f32 "
        "{%0,%1,%2,%3}, {%4,%5,%6,%7}, {%8,%9}, {%0,%1,%2,%3};\n"
        : "+f"(c[0]), "+f"(c[1]), "+f"(c[2]), "+f"(c[3])
        : "r"(a[0]), "r"(a[1]), "r"(a[2]), "r"(a[3]), "r"(b[0]), "r"(b[1]));
}
__device__ __forceinline__ void cp16(uint32_t dst, const void* src) {
    asm volatile("cp.async.cg.shared.global [%0], [%1], 16;" :: "r"(dst), "l"(src));
}
__device__ __forceinline__ void cp_commit() {
    asm volatile("cp.async.commit_group;" ::: "memory");
}
template <int N>
__device__ __forceinline__ void cp_wait() {
    asm volatile("cp.async.wait_group %0;" :: "n"(N) : "memory");
}
__device__ __forceinline__ uint2 pack4h(f16 a, f16 b, f16 c, f16 d) {
    uint2 r;
    uint16_t ua = *(uint16_t*)&a, ub = *(uint16_t*)&b;
    uint16_t uc = *(uint16_t*)&c, ud = *(uint16_t*)&d;
    r.x = (uint32_t)ua | ((uint32_t)ub << 16);
    r.y = (uint32_t)uc | ((uint32_t)ud << 16);
    return r;
}

// ---------------------------------------------------------------------------
// fp16x1 tensor-core GEMM (NT), cp.async 3-stage pipeline (R6 structure).
//   C[m][n] = sum_k A16[m][k]*W16[n][k] (+bias)
//   A16 = fp16(A), W16 = fp16(W); fp32 accumulate.
//   Error: independent A- and W-rounding ~2.8e-4 each -> ~4.4e-4 total
//   (calibrated against R15's measured 3.1e-4 for the W-only case).
// CTA 128x128, BK=32, 8 warps (4m x 2n), warp tile 32m x 64n, m16n8k16.
// smem per stage: [A | W], each 128 rows x 64 B,
// XOR swizzle: chunk' = chunk ^ ((row>>1)&3)  (16 B chunks, 4 per row).
// ---------------------------------------------------------------------------
static constexpr int BK      = 32;
static constexpr int KTILES  = Kdim / BK;        // 32
static constexpr int TSZ     = 128 * 64;          // 8192 B per array tile
static constexpr int STAGE   = 2 * TSZ;           // 16384 B
static constexpr int NSTAGE  = 3;
static constexpr int SMEM_TOTAL = NSTAGE * STAGE; // 49152 B

template <bool BIAS>
__global__ __launch_bounds__(256, 2)
void gemm_cp(const f16* __restrict__ A16, const f16* __restrict__ W16,
             const float* __restrict__ bias, float* __restrict__ C, int Ndim)
{
    extern __shared__ char smem[];
    const uint32_t smem_base = smem_u32(smem);
    const int tid  = threadIdx.x;
    const int wid  = tid >> 5;
    const int lane = tid & 31;
    const int wr   = wid & 3;           // m offset wr*32
    const int wc   = wid >> 2;          // n offset wc*64
    const int m0   = blockIdx.y * 128;
    const int n0   = blockIdx.x * 128;

    const f16* src[2] = { A16 + (size_t)m0 * Kdim, W16 + (size_t)n0 * Kdim };

    // ---- cp.async mapping (per thread: 4 chunks of 16 B per stage) ----
    auto load_stage = [&](int t, int buf) {
        const int k0 = t * BK;
        const uint32_t sb = smem_base + buf * STAGE;
        #pragma unroll
        for (int i = 0; i < 4; ++i) {
            const int idx = tid + i * 256;        // 0..1023
            const int arr = idx >> 9;             // 0,1
            const int id2 = idx & 511;
            const int row = id2 >> 2;
            const int ch  = id2 & 3;
            const uint32_t dst = sb + arr * TSZ + row * 64 +
                                 ((ch ^ ((row >> 1) & 3)) << 4);
            cp16(dst, src[arr] + (size_t)row * Kdim + k0 + ch * 8);
        }
        cp_commit();
    };

    // ---- ldmatrix offsets (within stage), per mi/gi and k-step ----
    const int tq   = lane >> 3;
    const int arow = (lane & 7) + (tq & 1) * 8;
    const int ach  = tq >> 1;
    const int brow = (tq >> 1) * 8 + (lane & 7);
    const int bch  = tq & 1;

    uint32_t offA[2][2], offB[4][2];
    #pragma unroll
    for (int mi = 0; mi < 2; ++mi) {
        const int row = wr * 32 + mi * 16 + arow;
        #pragma unroll
        for (int ks = 0; ks < 2; ++ks) {
            const int ch = ach + ks * 2;
            offA[mi][ks] = row * 64 + (((ch ^ ((row >> 1) & 3))) << 4);
        }
    }
    #pragma unroll
    for (int gi = 0; gi < 4; ++gi) {
        const int row = wc * 64 + gi * 16 + brow;
        #pragma unroll
        for (int ks = 0; ks < 2; ++ks) {
            const int ch = bch + ks * 2;
            offB[gi][ks] = row * 64 + (((ch ^ ((row >> 1) & 3))) << 4);
        }
    }

    float acc[2][8][4];
    #pragma unroll
    for (int i = 0; i < 2; ++i)
        #pragma unroll
        for (int j = 0; j < 8; ++j)
            #pragma unroll
            for (int e = 0; e < 4; ++e) acc[i][j][e] = 0.f;

    // ---- prologue: fill the pipeline ----
    load_stage(0, 0);
    load_stage(1, 1);
    load_stage(2, 2);

    for (int t = 0; t < KTILES; ++t) {
        cp_wait<2>();              // stage t landed
        __syncthreads();

        const int buf = t % NSTAGE;
        const uint32_t sa = smem_base + buf * STAGE;            // A base
        const uint32_t sw = sa + TSZ;                           // W base

        #pragma unroll
        for (int ks = 0; ks < 2; ++ks) {
            uint32_t af[2][4], bfr[4][4];
            #pragma unroll
            for (int mi = 0; mi < 2; ++mi)
                ldsm4(af[mi][0], af[mi][1], af[mi][2], af[mi][3], sa + offA[mi][ks]);
            #pragma unroll
            for (int gi = 0; gi < 4; ++gi)
                ldsm4(bfr[gi][0], bfr[gi][1], bfr[gi][2], bfr[gi][3], sw + offB[gi][ks]);
            #pragma unroll
            for (int mi = 0; mi < 2; ++mi)
                #pragma unroll
                for (int g = 0; g < 8; ++g)
                    mma_f16(acc[mi][g], af[mi], &bfr[g >> 1][(g & 1) * 2]);
        }

        __syncthreads();
        if (t + NSTAGE < KTILES) load_stage(t + NSTAGE, buf);
    }

    // ---- epilogue (m16n8 C-frag layout) ----
    const int crow = lane >> 2;
    const int ccol = (lane & 3) * 2;
    #pragma unroll
    for (int mi = 0; mi < 2; ++mi) {
        #pragma unroll
        for (int g = 0; g < 8; ++g) {
            const int col = n0 + wc * 64 + g * 8 + ccol;
            float b0 = BIAS ? bias[col]     : 0.f;
            float b1 = BIAS ? bias[col + 1] : 0.f;
            const int r0 = m0 + wr * 32 + mi * 16 + crow;
            float2 v0 = make_float2(acc[mi][g][0] + b0, acc[mi][g][1] + b1);
            float2 v1 = make_float2(acc[mi][g][2] + b0, acc[mi][g][3] + b1);
            *(float2*)(C + (size_t)r0 * Ndim + col)       = v0;
            *(float2*)(C + (size_t)(r0 + 8) * Ndim + col) = v1;
        }
    }
}

// ---------------------------------------------------------------------------
// Fused converts: x, w_qkv, w_fc -> fp16 (one launch)
// ---------------------------------------------------------------------------
static constexpr int N4X = Mrows * Dd / 4;   // x
static constexpr int N4Q = QKVN  * Dd / 4;   // w_qkv
static constexpr int N4F = Dd    * Dd / 4;   // w_fc
static constexpr int N4ALL = N4X + N4Q + N4F;

__device__ __forceinline__ void conv4h(const float* __restrict__ s,
                                       f16* __restrict__ h, int i) {
    float4 v = *(const float4*)(s + (size_t)i * 4);
    *(uint2*)(h + (size_t)i * 4) = pack4h(__float2half_rn(v.x), __float2half_rn(v.y),
                                          __float2half_rn(v.z), __float2half_rn(v.w));
}

__global__ void convert_all(const float* __restrict__ x,
                            const float* __restrict__ wq,
                            const float* __restrict__ wf,
                            f16* __restrict__ x16,
                            f16* __restrict__ wq16, f16* __restrict__ wf16)
{
    const int i = blockIdx.x * blockDim.x + threadIdx.x;
    if (i < N4X)               conv4h(x,  x16,  i);
    else if (i < N4X + N4Q)    conv4h(wq, wq16, i - N4X);
    else if (i < N4ALL)        conv4h(wf, wf16, i - N4X - N4Q);
}

// ---------------------------------------------------------------------------
// Attention (faithful-reshape 16x16 head-mixing), one CTA per (b, r, j):
//   q_prep[b, n, h, dh] = q[b, h*256 + n/16, (n%16)*64 + dh]
// fp32 qkv in, fp16 out (feeds FC GEMM A-side).
// ---------------------------------------------------------------------------
__global__ __launch_bounds__(256)
void attn16_kernel(const float* __restrict__ qkv, f16* __restrict__ o16)
{
    const int bxi = blockIdx.x;          // b*4096 + r*16 + j
    const int j = bxi & 15;
    const int r = (bxi >> 4) & 255;
    const int b = bxi >> 12;
    const int tid = threadIdx.x;
    const int hh = tid >> 4;
    const int lo = tid & 15;

    __shared__ float qs[16][64];
    __shared__ float ks[16][65];
    __shared__ float vs[16][64];
    __shared__ float ps[16][17];

    const size_t rowbase = ((size_t)b * 4096 + (size_t)hh * 256 + r) * 3072;
    const size_t outbase = ((size_t)b * 4096 + (size_t)hh * 256 + r) * 1024;
    const float scale = 0.125f;

    {
        const size_t c = (size_t)j * 64 + lo * 4;
        float4 q4 = *(const float4*)(qkv + rowbase + 0    + c);
        float4 k4 = *(const float4*)(qkv + rowbase + 1024 + c);
        float4 v4 = *(const float4*)(qkv + rowbase + 2048 + c);
        *(float4*)&qs[hh][lo * 4] = q4;
        ks[hh][lo * 4 + 0] = k4.x; ks[hh][lo * 4 + 1] = k4.y;
        ks[hh][lo * 4 + 2] = k4.z; ks[hh][lo * 4 + 3] = k4.w;
        *(float4*)&vs[hh][lo * 4] = v4;
    }
    __syncthreads();

    float s = 0.f;
    #pragma unroll
    for (int d = 0; d < 64; ++d) s = fmaf(qs[hh][d], ks[lo][d], s);
    s *= scale;

    float mx = s;
    #pragma unroll
    for (int off = 8; off; off >>= 1)
        mx = fmaxf(mx, __shfl_xor_sync(0xffffffffu, mx, off, 16));
    float e = __expf(s - mx);
    float sum = e;
    #pragma unroll
    for (int off = 8; off; off >>= 1)
        sum += __shfl_xor_sync(0xffffffffu, sum, off, 16);
    ps[hh][lo] = e / sum;
    __syncthreads();

    float4 o = make_float4(0.f, 0.f, 0.f, 0.f);
    #pragma unroll
    for (int g = 0; g < 16; ++g) {
        const float p = ps[hh][g];
        float4 v4 = *(const float4*)&vs[g][lo * 4];
        o.x = fmaf(p, v4.x, o.x); o.y = fmaf(p, v4.y, o.y);
        o.z = fmaf(p, v4.z, o.z); o.w = fmaf(p, v4.w, o.w);
    }
    *(uint2*)(o16 + outbase + (size_t)j * 64 + lo * 4) =
        pack4h(__float2half_rn(o.x), __float2half_rn(o.y),
               __float2half_rn(o.z), __float2half_rn(o.w));
}

// ---------------------------------------------------------------------------
// Launch
// ---------------------------------------------------------------------------
extern "C" void kernel_launch(void* const* d_in, const int* in_sizes, int n_in,
                              void* d_out, int out_size)
{
    const float* x     = (const float*)d_in[0];  // (4, 4096, 1024)
    const float* w_qkv = (const float*)d_in[1];  // (3072, 1024)
    const float* w_fc  = (const float*)d_in[2];  // (1024, 1024)
    const float* b_fc  = (const float*)d_in[3];  // (1024,)
    float* out = (float*)d_out;                  // (4, 4096, 1024)

    float *qkv_p; f16 *x16_p, *a16_p, *wq_p, *wf_p;
    cudaGetSymbolAddress((void**)&qkv_p, g_qkv);
    cudaGetSymbolAddress((void**)&x16_p, g_x16);
    cudaGetSymbolAddress((void**)&a16_p, g_a16);
    cudaGetSymbolAddress((void**)&wq_p,  g_wq16);
    cudaGetSymbolAddress((void**)&wf_p,  g_wf16);

    cudaFuncSetAttribute(gemm_cp<false>, cudaFuncAttributeMaxDynamicSharedMemorySize, SMEM_TOTAL);
    cudaFuncSetAttribute(gemm_cp<true>,  cudaFuncAttributeMaxDynamicSharedMemorySize, SMEM_TOTAL);

    // 0) converts: x, w_qkv, w_fc -> fp16 (single fused launch)
    convert_all<<<(N4ALL + 255) / 256, 256>>>(x, w_qkv, w_fc, x16_p, wq_p, wf_p);

    // 1) qkv = x @ w_qkv^T  (fp32 out, M=16384, N=3072)
    gemm_cp<false><<<dim3(QKVN / 128, Mrows / 128), 256, SMEM_TOTAL>>>(
        x16_p, wq_p, nullptr, qkv_p, QKVN);

    // 2) 16x16 head-mix attention -> fp16 (one CTA per (b,r,j))
    attn16_kernel<<<Bb * 256 * 16, 256>>>(qkv_p, a16_p);

    // 3) out = attn @ w_fc^T + b_fc  (M=16384, N=1024)
    gemm_cp<true><<<dim3(Dd / 128, Mrows / 128), 256, SMEM_TOTAL>>>(
        a16_p, wf_p, b_fc, out, Dd);
}